// round 2
// baseline (speedup 1.0000x reference)
#include <cuda_runtime.h>
#include <math.h>

#define THRESH 1e-4f
#define MAXBP  8192
#define BIGL   0x40000000

// ---- kA (Z scan + anomaly scan + walk) config ----
#define BLKA 256
#define CHA  32
#define WUP  48
#define TILE (BLKA*CHA)           // 8192 steps per block
#define SZN  (TILE + 32)          // logical smem Z indices 0..8223
#define SZPHYS (SZN + (SZN>>5) + 2)

// ---- k4 (J/H emit) config ----
#define BLKB  256
#define STEPS 9                   // odd -> conflict-friendly strides
#define NB    (BLKB*STEPS)        // 2304 steps per block
#define HALO  8

// Scratch (no allocations allowed); static-init zero for first run,
// self-reset by the last kA block for graph replays.
__device__ int g_anom_n = 0;
__device__ int g_ticket = 0;
__device__ int g_anom_p[MAXBP];
__device__ int g_anom_l[MAXBP];
__device__ int g_K;
__device__ int g_P[MAXBP];
__device__ int g_Q[MAXBP];

__device__ __forceinline__ int skew(int i) { return i + (i >> 5); }

// ============================================================================
// kA: fused Z-scan (chunked, warm-up converged), anomaly scan, orbit walk.
// ============================================================================
__global__ void kA(const float* __restrict__ X, const float* __restrict__ pr,
                   float* __restrict__ Z, int T) {
    __shared__ float sZ[SZPHYS];
    int nsteps = T - 1;
    int B = blockIdx.x * TILE;
    int si = B + threadIdx.x * CHA;

    float w1 = (float)tanh((double)pr[0]);
    float w2 = (float)tanh((double)pr[1]);
    float w3 = pr[2], w4 = pr[3];
    float w4_2 = 2.0f * pr[3];

    // ---- phase 1: h values into smem (+global Z) ----
    if (si < nsteps) {
        int t0 = si - WUP; if (t0 < 0) t0 = 0;
        float h = 0.f;
        for (int t = t0; t < si; ++t) {
            float x  = X[t];
            float cc = fmaf(w3, x * x, w1 * x);
            float u  = fmaf(w4, h, w2);
            h = fmaf(h, u, cc);
        }
        sZ[skew(si - B)] = h;                 // pre-step value = Z[si]
        if (si == 0) Z[0] = 0.f;
        int e = si + CHA; if (e > nsteps) e = nsteps;
        for (int t = si; t < e; ++t) {
            float x  = X[t];
            float cc = fmaf(w3, x * x, w1 * x);
            float u  = fmaf(w4, h, w2);
            h = fmaf(h, u, cc);
            Z[t + 1] = h;
            sZ[skew(t + 1 - B)] = h;
        }
        // halo: last thread extends 31 steps (bitwise == next block's values)
        if (threadIdx.x == BLKA - 1) {
            int he = e + 31; if (he > nsteps) he = nsteps;
            for (int t = e; t < he; ++t) {
                float x  = X[t];
                float cc = fmaf(w3, x * x, w1 * x);
                float u  = fmaf(w4, h, w2);
                h = fmaf(h, u, cc);
                sZ[skew(t + 1 - B)] = h;
            }
        }
    }
    __syncthreads();

    // ---- phase 2: anomaly scan (window length != 6), exact fp32 semantics ----
    if (si < nsteps) {
        int pe = si + CHA; if (pe > nsteps) pe = nsteps;
        for (int p = si; p < pe; ++p) {
            if (p + 6 <= nsteps) {
                // fast path: length == 6  <=>  d1..d5 >= TH  and  d6 < TH
                float d = 1.f; bool ok = true;
#pragma unroll
                for (int j = 0; j < 6; ++j) {
                    float h = sZ[skew(p + j - B)];
                    float a = __fadd_rn(w2, __fmul_rn(w4_2, h));
                    d = __fmul_rn(d, fabsf(a));
                    if (j < 5) ok = ok && (d >= THRESH);
                }
                if (ok && (d < THRESH)) continue;     // normal window
            }
            // exact (rare) path — replicate the emit loop's decay recurrence
            float d = 1.f; int l = -1;
#pragma unroll 1
            for (int j = 0; j < 32; ++j) {
                int t = p + j;
                if (t >= nsteps) break;
                float h = sZ[skew(t - B)];
                float a = __fadd_rn(w2, __fmul_rn(w4_2, h));
                d = __fmul_rn(d, fabsf(a));
                if (d < THRESH) { l = j + 1; break; }
            }
            if (l != 6) {
                int i = atomicAdd(&g_anom_n, 1);
                if (i < MAXBP) { g_anom_p[i] = p; g_anom_l[i] = (l < 0) ? BIGL : l; }
            }
        }
    }
    __threadfence();
    __syncthreads();

    // ---- phase 3: last finished block walks the reset orbit ----
    if (threadIdx.x == 0) {
        int tk = atomicAdd(&g_ticket, 1);
        if (tk == (int)gridDim.x - 1) {
            int n = g_anom_n; if (n > MAXBP) n = MAXBP;
            for (int i = 1; i < n; ++i) {                 // tiny insertion sort
                int p = g_anom_p[i], ll = g_anom_l[i], j = i - 1;
                while (j >= 0 && g_anom_p[j] > p) {
                    g_anom_p[j + 1] = g_anom_p[j]; g_anom_l[j + 1] = g_anom_l[j]; --j;
                }
                g_anom_p[j + 1] = p; g_anom_l[j + 1] = ll;
            }
            int pos = 0, K = 0;
            for (int i = 0; i < n && K < MAXBP; ++i) {
                int p = g_anom_p[i];
                if (p < pos) continue;
                if ((p - pos) % 6 != 0) continue;         // not on the orbit
                int ll = g_anom_l[i];
                g_P[K] = p;
                if (ll >= BIGL) { g_Q[K] = 0x7fffffff; ++K; break; }
                g_Q[K] = p + ll; pos = p + ll; ++K;
            }
            g_K = K;
            g_anom_n = 0;        // self-reset for next graph replay
            g_ticket = 0;
        }
    }
}

// Given step s, start of the reset window containing s.
__device__ __forceinline__ int window_start(int s) {
    int K = g_K;
    if (K == 0 || s < g_P[0]) return s - s % 6;
    int lo = 0, hi = K - 1;
    while (lo < hi) {                                     // last k: P[k] <= s
        int mid = (lo + hi + 1) >> 1;
        if (g_P[mid] <= s) lo = mid; else hi = mid - 1;
    }
    int q = g_Q[lo];
    if (s < q) return g_P[lo];
    int r = s - q;
    return q + (r - r % 6);
}

// ============================================================================
// k4: J/H emit with shared-memory staging -> fully coalesced output stores.
// ============================================================================
__global__ void k4_main(const float* __restrict__ X, const float* __restrict__ Z,
                        const float* __restrict__ pr,
                        float* __restrict__ outJ, float* __restrict__ outH, int T) {
    extern __shared__ float sm[];
    float* sX  = sm;                        // NB+HALO
    float* sZm = sm + (NB + HALO);          // NB+HALO
    float* sJ  = sm + 2 * (NB + HALO);      // NB*4  (16B-aligned offset)
    float* sH  = sJ + NB * 4;               // NB*10
    int nsteps = T - 1;
    int s0 = blockIdx.x * NB;
    int tid = threadIdx.x;

    if (blockIdx.x == 0 && tid == 0) {      // row 0 of J and H = 0
        ((float4*)outJ)[0] = make_float4(0, 0, 0, 0);
        float4 z4 = make_float4(0, 0, 0, 0);
        ((float4*)outH)[0] = z4; ((float4*)outH)[1] = z4;
        ((float4*)outH)[2] = z4; ((float4*)outH)[3] = z4;
    }

    // stage X/Z coalesced
    for (int i = tid; i < NB + HALO; i += BLKB) {
        int t = s0 - HALO + i;
        float xv = 0.f, hv = 0.f;
        if (t >= 0 && t < nsteps) { xv = X[t]; hv = Z[t]; }
        sX[i] = xv; sZm[i] = hv;
    }
    __syncthreads();

    int s = s0 + tid * STEPS;
    if (s < nsteps) {
        float w1 = (float)tanh((double)pr[0]);
        float w2 = (float)tanh((double)pr[1]);
        float w4 = pr[3];
        float dt1  = 1.f - w1 * w1,  dt2  = 1.f - w2 * w2;
        float d2t1 = -2.f * w1 * dt1, d2t2 = -2.f * w2 * dt2;
        float w4_2 = 2.f * w4;

        int w = window_start(s);
        int e = s + STEPS; if (e > nsteps) e = nsteps;

        float J0 = 0, J1 = 0, J2 = 0, J3 = 0;
        float H00 = 0, H01 = 0, H02 = 0, H03 = 0, H11 = 0;
        float H12 = 0, H13 = 0, H22 = 0, H23 = 0, H33 = 0;
        float dec = 1.f;

#pragma unroll 1
        for (int t = w; t < e; ++t) {
            int li = t - s0 + HALO;
            float x, h;
            if (li >= 0) { x = sX[li]; h = sZm[li]; }
            else         { x = X[t];   h = Z[t];   }     // pathological far window
            float a  = __fadd_rn(w2, __fmul_rn(w4_2, h));
            float dn = __fmul_rn(dec, fabsf(a));
            bool  rs = dn < THRESH;
            float g3 = 2.f * h;
            float nJ0 = fmaf(a, J0, x * dt1);
            float nJ1 = fmaf(a, J1, h * dt2);
            float nJ2 = fmaf(a, J2, x * x);
            float nJ3 = fmaf(a, J3, h * h);
            float nH00 = fmaf(a, H00, x * d2t1);
            float nH01 = fmaf(a, H01, dt2 * J0);
            float nH02 = a * H02;
            float nH03 = fmaf(a, H03, g3 * J0);
            float nH11 = fmaf(a, H11, fmaf(2.f * dt2, J1, h * d2t2));
            float nH12 = fmaf(a, H12, dt2 * J2);
            float nH13 = fmaf(a, H13, fmaf(dt2, J3, g3 * J1));
            float nH22 = a * H22;
            float nH23 = fmaf(a, H23, g3 * J2);
            float nH33 = fmaf(a, H33, (2.f * g3) * J3);
            if (rs) {
                J0 = J1 = J2 = J3 = 0.f;
                H00 = H01 = H02 = H03 = H11 = 0.f;
                H12 = H13 = H22 = H23 = H33 = 0.f;
                dec = 1.f;
            } else {
                J0 = nJ0; J1 = nJ1; J2 = nJ2; J3 = nJ3;
                H00 = nH00; H01 = nH01; H02 = nH02; H03 = nH03; H11 = nH11;
                H12 = nH12; H13 = nH13; H22 = nH22; H23 = nH23; H33 = nH33;
                dec = dn;
            }
            if (t >= s) {                                 // stage post-reset values
                int lt = t - s0;
                *(float4*)&sJ[lt * 4] = make_float4(J0, J1, J2, J3);
                float* hp = &sH[lt * 10];
                hp[0] = H00; hp[1] = H01; hp[2] = H02; hp[3] = H03; hp[4] = H11;
                hp[5] = H12; hp[6] = H13; hp[7] = H22; hp[8] = H23; hp[9] = H33;
            }
        }
    }
    __syncthreads();

    int cnt = nsteps - s0; if (cnt > NB) cnt = NB;
    // J writeout: coalesced float4 stream
    for (int i = tid; i < cnt; i += BLKB) {
        float4 v = *(float4*)&sJ[i * 4];
        ((float4*)outJ)[(size_t)(s0 + 1) + i] = v;
    }
    // H writeout: coalesced float4 stream (reconstruct symmetric rows)
    int tot = cnt * 4;
    for (int i = tid; i < tot; i += BLKB) {
        int lt = i >> 2, r = i & 3;
        const float* hp = &sH[lt * 10];
        float4 v;
        if      (r == 0) v = make_float4(hp[0], hp[1], hp[2], hp[3]);
        else if (r == 1) v = make_float4(hp[1], hp[4], hp[5], hp[6]);
        else if (r == 2) v = make_float4(hp[2], hp[5], hp[7], hp[8]);
        else             v = make_float4(hp[3], hp[6], hp[8], hp[9]);
        ((float4*)outH)[(size_t)(s0 + 1) * 4 + i] = v;
    }
}

extern "C" void kernel_launch(void* const* d_in, const int* in_sizes, int n_in,
                              void* d_out, int out_size) {
    const float* X  = (const float*)d_in[0];
    const float* pr = (const float*)d_in[1];
    int T = in_sizes[0];
    float* out = (float*)d_out;
    float* Z = out;                        // [T]
    float* J = out + (size_t)T;            // [T,4]
    float* H = out + (size_t)5 * T;        // [T,4,4]

    static bool configured = false;
    const int SMEMB = (2 * (NB + HALO) + NB * 14) * (int)sizeof(float);
    if (!configured) {
        cudaFuncSetAttribute(k4_main, cudaFuncAttributeMaxDynamicSharedMemorySize, SMEMB);
        configured = true;
    }

    int nsteps = T - 1;
    int gA = (nsteps + TILE - 1) / TILE;
    kA<<<gA, BLKA>>>(X, pr, Z, T);
    int gB = (nsteps + NB - 1) / NB;
    k4_main<<<gB, BLKB, SMEMB>>>(X, Z, pr, J, H, T);
}

// round 3
// speedup vs baseline: 1.5652x; 1.5652x over previous
#include <cuda_runtime.h>
#include <math.h>

#define THRESH 1e-4f
#define MAXBP  8192
#define BIGL   0x40000000

// ---- kA (Z scan + anomaly scan + walk) config ----
#define BLKA 256
#define CHA  16
#define WUP  48
#define TILE (BLKA*CHA)            // 4096 steps per block
#define XN   (TILE + WUP + 32)     // staged X: [B-WUP, B+TILE+31]
#define SZN  (TILE + 32)           // staged Z: logical 0..TILE+31

// ---- k4 (J/H emit) config ----
#define BLKB  256
#define HALOB 32

// Scratch (no allocations); zero-init for first run, self-reset for replays.
__device__ int g_anom_n = 0;
__device__ int g_ticket = 0;
__device__ int g_anom_p[MAXBP];
__device__ int g_anom_l[MAXBP];
__device__ int g_K;
__device__ int g_P[MAXBP];
__device__ int g_Q[MAXBP];

__device__ __forceinline__ int skew(int i) { return i + (i >> 5); }

// ============================================================================
// kA: fused Z-scan (chunked, warm-up converged) + anomaly scan + orbit walk.
// All serial-loop operands come from smem (coalesced-staged, skewed).
// ============================================================================
__global__ __launch_bounds__(BLKA) void kA(const float* __restrict__ X,
                                           const float* __restrict__ pr,
                                           float* __restrict__ Z, int T) {
    __shared__ float sX[XN + (XN >> 5) + 2];
    __shared__ float sZ[SZN + (SZN >> 5) + 2];
    int nsteps = T - 1;
    int B = blockIdx.x * TILE;
    int tid = threadIdx.x;

    // stage X coalesced: logical i <-> global t = B - WUP + i
    for (int i = tid; i < XN; i += BLKA) {
        int t = B - WUP + i;
        sX[skew(i)] = (t >= 0 && t < T) ? X[t] : 0.f;
    }
    __syncthreads();

    float w1 = (float)tanh((double)pr[0]);
    float w2 = (float)tanh((double)pr[1]);
    float w3 = pr[2], w4 = pr[3];
    float w4_2 = 2.0f * pr[3];

    int si = B + tid * CHA;
    // ---- phase 1: h chain into sZ ----
    if (si < nsteps) {
        int t0 = si - WUP; if (t0 < 0) t0 = 0;
        float h = 0.f;
        for (int t = t0; t < si; ++t) {
            float x  = sX[skew(t - B + WUP)];
            float cc = fmaf(w3, x * x, w1 * x);
            float u  = fmaf(w4, h, w2);
            h = fmaf(h, u, cc);
        }
        sZ[skew(si - B)] = h;                       // Z[si] (pre-step value)
        int e = si + CHA; if (e > nsteps) e = nsteps;
        for (int t = si; t < e; ++t) {
            float x  = sX[skew(t - B + WUP)];
            float cc = fmaf(w3, x * x, w1 * x);
            float u  = fmaf(w4, h, w2);
            h = fmaf(h, u, cc);
            sZ[skew(t + 1 - B)] = h;
        }
        if (tid == BLKA - 1) {                      // 31-step halo extension
            int he = e + 31; if (he > nsteps) he = nsteps;
            for (int t = e; t < he; ++t) {
                float x  = sX[skew(t - B + WUP)];
                float cc = fmaf(w3, x * x, w1 * x);
                float u  = fmaf(w4, h, w2);
                h = fmaf(h, u, cc);
                sZ[skew(t + 1 - B)] = h;
            }
        }
    }
    __syncthreads();

    // ---- coalesced Z writeout from smem ----
    if (B == 0 && tid == 0) Z[0] = 0.f;
    for (int i = tid; i < TILE; i += BLKA) {
        int g = B + 1 + i;
        if (g <= nsteps) Z[g] = sZ[skew(1 + i)];
    }

    // ---- phase 2: anomaly scan (window length != 6), exact fp32 semantics ----
    if (si < nsteps) {
        int pe = si + CHA; if (pe > nsteps) pe = nsteps;
        for (int p = si; p < pe; ++p) {
            if (p + 6 <= nsteps) {
                float d = 1.f; bool ok = true;
#pragma unroll
                for (int j = 0; j < 6; ++j) {
                    float h = sZ[skew(p + j - B)];
                    float a = __fadd_rn(w2, __fmul_rn(w4_2, h));
                    d = __fmul_rn(d, fabsf(a));
                    if (j < 5) ok = ok && (d >= THRESH);
                }
                if (ok && (d < THRESH)) continue;   // normal 6-window
            }
            float d = 1.f; int l = -1;              // rare exact path
#pragma unroll 1
            for (int j = 0; j < 32; ++j) {
                int t = p + j;
                if (t >= nsteps) break;
                float h = sZ[skew(t - B)];
                float a = __fadd_rn(w2, __fmul_rn(w4_2, h));
                d = __fmul_rn(d, fabsf(a));
                if (d < THRESH) { l = j + 1; break; }
            }
            if (l != 6) {
                int i = atomicAdd(&g_anom_n, 1);
                if (i < MAXBP) { g_anom_p[i] = p; g_anom_l[i] = (l < 0) ? BIGL : l; }
            }
        }
    }
    __threadfence();
    __syncthreads();

    // ---- phase 3: last finished block walks the reset orbit ----
    if (tid == 0) {
        int tk = atomicAdd(&g_ticket, 1);
        if (tk == (int)gridDim.x - 1) {
            int n = g_anom_n; if (n > MAXBP) n = MAXBP;
            for (int i = 1; i < n; ++i) {           // tiny insertion sort
                int p = g_anom_p[i], ll = g_anom_l[i], j = i - 1;
                while (j >= 0 && g_anom_p[j] > p) {
                    g_anom_p[j + 1] = g_anom_p[j]; g_anom_l[j + 1] = g_anom_l[j]; --j;
                }
                g_anom_p[j + 1] = p; g_anom_l[j + 1] = ll;
            }
            int pos = 0, K = 0;
            for (int i = 0; i < n && K < MAXBP; ++i) {
                int p = g_anom_p[i];
                if (p < pos) continue;
                if ((p - pos) % 6 != 0) continue;   // not on the orbit
                int ll = g_anom_l[i];
                g_P[K] = p;
                if (ll >= BIGL) { g_Q[K] = 0x7fffffff; ++K; break; }
                g_Q[K] = p + ll; pos = p + ll; ++K;
            }
            g_K = K;
            g_anom_n = 0;                           // reset for next replay
            g_ticket = 0;
        }
    }
}

// Start of the reset window containing step s.
__device__ __forceinline__ int window_start(int s) {
    int K = g_K;
    if (K == 0 || s < g_P[0]) return s - s % 6;
    int lo = 0, hi = K - 1;
    while (lo < hi) {                               // last k with P[k] <= s
        int mid = (lo + hi + 1) >> 1;
        if (g_P[mid] <= s) lo = mid; else hi = mid - 1;
    }
    int q = g_Q[lo];
    if (s < q) return g_P[lo];
    int r = s - q;
    return q + (r - r % 6);
}

// ============================================================================
// k4: one output step per thread. Rebuild window (<= ~6 steps), emit once.
// J: direct perfectly-coalesced float4. H: smem-staged coalesced float4 stream.
// ============================================================================
__global__ __launch_bounds__(BLKB) void k4_main(const float* __restrict__ X,
                                                const float* __restrict__ Z,
                                                const float* __restrict__ pr,
                                                float* __restrict__ outJ,
                                                float* __restrict__ outH, int T) {
    __shared__ float sX4[BLKB + HALOB];
    __shared__ float sZ4[BLKB + HALOB];
    __shared__ float sH[BLKB * 11];
    int nsteps = T - 1;
    int s0 = blockIdx.x * BLKB;
    int tid = threadIdx.x;

    if (blockIdx.x == 0 && tid == 0) {              // row 0 of J and H = 0
        ((float4*)outJ)[0] = make_float4(0, 0, 0, 0);
        float4 z4 = make_float4(0, 0, 0, 0);
        ((float4*)outH)[0] = z4; ((float4*)outH)[1] = z4;
        ((float4*)outH)[2] = z4; ((float4*)outH)[3] = z4;
    }

    for (int i = tid; i < BLKB + HALOB; i += BLKB) {  // stage X/Z coalesced
        int t = s0 - HALOB + i;
        float xv = 0.f, hv = 0.f;
        if (t >= 0 && t < nsteps) { xv = X[t]; hv = Z[t]; }
        sX4[i] = xv; sZ4[i] = hv;
    }
    __syncthreads();

    int s = s0 + tid;
    if (s < nsteps) {
        float w1 = (float)tanh((double)pr[0]);
        float w2 = (float)tanh((double)pr[1]);
        float w4 = pr[3];
        float dt1  = 1.f - w1 * w1,  dt2  = 1.f - w2 * w2;
        float d2t1 = -2.f * w1 * dt1, d2t2 = -2.f * w2 * dt2;
        float w4_2 = 2.f * w4;

        int w = window_start(s);

        float J0 = 0, J1 = 0, J2 = 0, J3 = 0;
        float H00 = 0, H01 = 0, H02 = 0, H03 = 0, H11 = 0;
        float H12 = 0, H13 = 0, H22 = 0, H23 = 0, H33 = 0;
        float dec = 1.f;

#pragma unroll 1
        for (int t = w; t <= s; ++t) {
            int li = t - s0 + HALOB;
            float x, h;
            if (li >= 0) { x = sX4[li]; h = sZ4[li]; }
            else         { x = X[t];    h = Z[t];   }   // pathological far window
            float a  = __fadd_rn(w2, __fmul_rn(w4_2, h));
            float dn = __fmul_rn(dec, fabsf(a));
            bool  rs = dn < THRESH;
            float g3 = 2.f * h;
            float nJ0 = fmaf(a, J0, x * dt1);
            float nJ1 = fmaf(a, J1, h * dt2);
            float nJ2 = fmaf(a, J2, x * x);
            float nJ3 = fmaf(a, J3, h * h);
            float nH00 = fmaf(a, H00, x * d2t1);
            float nH01 = fmaf(a, H01, dt2 * J0);
            float nH02 = a * H02;
            float nH03 = fmaf(a, H03, g3 * J0);
            float nH11 = fmaf(a, H11, fmaf(2.f * dt2, J1, h * d2t2));
            float nH12 = fmaf(a, H12, dt2 * J2);
            float nH13 = fmaf(a, H13, fmaf(dt2, J3, g3 * J1));
            float nH22 = a * H22;
            float nH23 = fmaf(a, H23, g3 * J2);
            float nH33 = fmaf(a, H33, (2.f * g3) * J3);
            if (rs) {
                J0 = J1 = J2 = J3 = 0.f;
                H00 = H01 = H02 = H03 = H11 = 0.f;
                H12 = H13 = H22 = H23 = H33 = 0.f;
                dec = 1.f;
            } else {
                J0 = nJ0; J1 = nJ1; J2 = nJ2; J3 = nJ3;
                H00 = nH00; H01 = nH01; H02 = nH02; H03 = nH03; H11 = nH11;
                H12 = nH12; H13 = nH13; H22 = nH22; H23 = nH23; H33 = nH33;
                dec = dn;
            }
        }
        // emit step s -> output row s+1
        ((float4*)outJ)[s + 1] = make_float4(J0, J1, J2, J3);
        float* hp = &sH[tid * 11];
        hp[0] = H00; hp[1] = H01; hp[2] = H02; hp[3] = H03; hp[4] = H11;
        hp[5] = H12; hp[6] = H13; hp[7] = H22; hp[8] = H23; hp[9] = H33;
    }
    __syncthreads();

    int cnt = nsteps - s0; if (cnt > BLKB) cnt = BLKB;
    if (cnt < 0) cnt = 0;
    int tot = cnt * 4;                              // coalesced H writeout
    for (int i = tid; i < tot; i += BLKB) {
        int lt = i >> 2, r = i & 3;
        const float* hp = &sH[lt * 11];
        float4 v;
        if      (r == 0) v = make_float4(hp[0], hp[1], hp[2], hp[3]);
        else if (r == 1) v = make_float4(hp[1], hp[4], hp[5], hp[6]);
        else if (r == 2) v = make_float4(hp[2], hp[5], hp[7], hp[8]);
        else             v = make_float4(hp[3], hp[6], hp[8], hp[9]);
        ((float4*)outH)[(size_t)(s0 + 1) * 4 + i] = v;
    }
}

extern "C" void kernel_launch(void* const* d_in, const int* in_sizes, int n_in,
                              void* d_out, int out_size) {
    const float* X  = (const float*)d_in[0];
    const float* pr = (const float*)d_in[1];
    int T = in_sizes[0];
    float* out = (float*)d_out;
    float* Z = out;                        // [T]
    float* J = out + (size_t)T;            // [T,4]
    float* H = out + (size_t)5 * T;        // [T,4,4]

    int nsteps = T - 1;
    int gA = (nsteps + TILE - 1) / TILE;
    kA<<<gA, BLKA>>>(X, pr, Z, T);
    int gB = (nsteps + BLKB - 1) / BLKB;
    k4_main<<<gB, BLKB>>>(X, Z, pr, J, H, T);
}